// round 17
// baseline (speedup 1.0000x reference)
#include <cuda_runtime.h>
#include <cuda_fp16.h>
#include <cstdint>

#define BN 8
#define IC 512
#define OC 512
#define HH 32
#define WW 32
#define NTL 2048    // total 2x2 output tiles = BN * 16 * 16

#define RC_DENSE 0.04419417382415922f     // 1/sqrt(512)
#define RC_CONV  0.014731391274719739f    // 1/sqrt(9*512)

// ---------------- device scratch (no runtime allocation) ----------------
__device__ float g_style[BN * IC];
__device__ float g_scale[BN * OC];
__device__ float g_ss[IC * OC];
__device__ __align__(128) __half g_U[16 * OC * IC];   // [j][oc][ic]
__device__ __align__(128) __half g_V[16 * NTL * IC];  // [j][tile][ic]

// ---------------- prologue: style / ss / demod ----------------
__global__ void style_kernel(const float* __restrict__ w,
                             const float* __restrict__ dense_w,
                             const float* __restrict__ dense_b) {
    __shared__ float wrow[IC];
    int b = blockIdx.x;
    for (int j = threadIdx.x; j < IC; j += blockDim.x) wrow[j] = w[b * IC + j];
    __syncthreads();
    for (int i = threadIdx.x; i < IC; i += blockDim.x) {
        float acc = 0.f;
        #pragma unroll 8
        for (int j = 0; j < IC; j++) acc = fmaf(wrow[j], dense_w[j * IC + i], acc);
        g_style[b * IC + i] = RC_DENSE * acc + dense_b[i] + 1.0f;
    }
}

__global__ void ss_kernel(const float* __restrict__ conv_w) {
    int idx = blockIdx.x * blockDim.x + threadIdx.x;
    if (idx >= IC * OC) return;
    float s = 0.f;
    #pragma unroll
    for (int k = 0; k < 9; k++) {
        float v = conv_w[k * IC * OC + idx];
        s = fmaf(v, v, s);
    }
    g_ss[idx] = s;
}

__global__ __launch_bounds__(256)
void demod_kernel() {
    __shared__ float s2[BN * IC];
    __shared__ float part[8 * BN * 32];
    const int t = threadIdx.x;
    const int oc0 = blockIdx.x * 32;
    for (int e = t; e < BN * IC; e += 256) {
        float s = g_style[e];
        s2[e] = s * s;
    }
    __syncthreads();
    const int oc_l = t & 31, oct = t >> 5;
    float acc[BN];
    #pragma unroll
    for (int b = 0; b < BN; b++) acc[b] = 0.f;
    for (int ic = oct * 64; ic < oct * 64 + 64; ic++) {
        float ssv = g_ss[(size_t)ic * OC + oc0 + oc_l];
        #pragma unroll
        for (int b = 0; b < BN; b++) acc[b] = fmaf(s2[b * IC + ic], ssv, acc[b]);
    }
    #pragma unroll
    for (int b = 0; b < BN; b++) part[(oct * BN + b) * 32 + oc_l] = acc[b];
    __syncthreads();
    const int b = t >> 5, ocl2 = t & 31;
    float s = 0.f;
    #pragma unroll
    for (int o = 0; o < 8; o++) s += part[(o * BN + b) * 32 + ocl2];
    g_scale[b * OC + oc0 + ocl2] = RC_CONV * rsqrtf(RC_CONV * RC_CONV * s + 1e-8f);
}

// ---------------- weight transform: U = G g G^T -> [j][oc][ic] fp16 ----------------
__global__ __launch_bounds__(1024)
void uw_kernel(const float* __restrict__ conv_w) {
    __shared__ float f[9][32][33];
    int ic0 = blockIdx.x * 32, oc0 = blockIdx.y * 32;
    int t = threadIdx.x;
    for (int e = t; e < 9 * 1024; e += 1024) {
        int k = e >> 10, r = (e >> 5) & 31, c = e & 31;
        f[k][r][c] = conv_w[(size_t)k * IC * OC + (size_t)(ic0 + r) * OC + oc0 + c];
    }
    __syncthreads();
    int ol = t >> 5, il = t & 31;
    float g[9];
    #pragma unroll
    for (int k = 0; k < 9; k++) g[k] = f[k][il][ol];
    float tr[4][3];
    #pragma unroll
    for (int c = 0; c < 3; c++) {
        tr[0][c] = g[c];
        tr[1][c] = 0.5f * (g[c] + g[3 + c] + g[6 + c]);
        tr[2][c] = 0.5f * (g[c] - g[3 + c] + g[6 + c]);
        tr[3][c] = g[6 + c];
    }
    size_t base = (size_t)(oc0 + ol) * IC + ic0 + il;
    #pragma unroll
    for (int i = 0; i < 4; i++) {
        float u0 = tr[i][0];
        float u1 = 0.5f * (tr[i][0] + tr[i][1] + tr[i][2]);
        float u2 = 0.5f * (tr[i][0] - tr[i][1] + tr[i][2]);
        float u3 = tr[i][2];
        g_U[(size_t)(i * 4 + 0) * OC * IC + base] = __float2half_rn(u0);
        g_U[(size_t)(i * 4 + 1) * OC * IC + base] = __float2half_rn(u1);
        g_U[(size_t)(i * 4 + 2) * OC * IC + base] = __float2half_rn(u2);
        g_U[(size_t)(i * 4 + 3) * OC * IC + base] = __float2half_rn(u3);
    }
}

// ---------------- data transform: V = B^T (style*x) B -> [j][tile][ic] fp16 ----------
__global__ __launch_bounds__(256)
void vx_kernel(const float* __restrict__ x) {
    __shared__ float xs[16][4][33];
    __shared__ unsigned short sv[16 * 16 * 18];
    int blk = blockIdx.x;            // b*16 + ti
    int b = blk >> 4, ti = blk & 15;
    int t = threadIdx.x;
    int icl_t = t >> 4, tj_t = t & 15;
    int tbase = blk << 4;

    for (int cc = 0; cc < 32; cc++) {
        int ic0 = cc * 16;
        __syncthreads();
        #pragma unroll
        for (int i = 0; i < 8; i++) {
            int e = t + i * 256;
            int icl = e >> 7, row = (e >> 5) & 3, w = e & 31;
            int h = 2 * ti - 1 + row;
            float v = 0.f;
            if ((unsigned)h < HH)
                v = x[(((size_t)b * IC + ic0 + icl) * HH + h) * WW + w] * g_style[b * IC + ic0 + icl];
            xs[icl][row][w] = v;
        }
        __syncthreads();
        {
            float d[4][4];
            #pragma unroll
            for (int r = 0; r < 4; r++)
                #pragma unroll
                for (int c = 0; c < 4; c++) {
                    int w = 2 * tj_t - 1 + c;
                    d[r][c] = ((unsigned)w < WW) ? xs[icl_t][r][w] : 0.f;
                }
            float tr[4][4];
            #pragma unroll
            for (int c = 0; c < 4; c++) {
                tr[0][c] = d[0][c] - d[2][c];
                tr[1][c] = d[1][c] + d[2][c];
                tr[2][c] = d[2][c] - d[1][c];
                tr[3][c] = d[1][c] - d[3][c];
            }
            #pragma unroll
            for (int i = 0; i < 4; i++) {
                float v0 = tr[i][0] - tr[i][2];
                float v1 = tr[i][1] + tr[i][2];
                float v2 = tr[i][2] - tr[i][1];
                float v3 = tr[i][1] - tr[i][3];
                sv[((i * 4 + 0) * 16 + tj_t) * 18 + icl_t] = __half_as_ushort(__float2half_rn(v0));
                sv[((i * 4 + 1) * 16 + tj_t) * 18 + icl_t] = __half_as_ushort(__float2half_rn(v1));
                sv[((i * 4 + 2) * 16 + tj_t) * 18 + icl_t] = __half_as_ushort(__float2half_rn(v2));
                sv[((i * 4 + 3) * 16 + tj_t) * 18 + icl_t] = __half_as_ushort(__float2half_rn(v3));
            }
        }
        __syncthreads();
        {
            int j = t >> 4, tj = t & 15;
            const unsigned int* s32 = (const unsigned int*)&sv[(j * 16 + tj) * 18];
            uint4 p0 = make_uint4(s32[0], s32[1], s32[2], s32[3]);
            uint4 p1 = make_uint4(s32[4], s32[5], s32[6], s32[7]);
            uint4* dst = (uint4*)(g_V + ((size_t)j * NTL + tbase + tj) * IC + ic0);
            dst[0] = p0; dst[1] = p1;
        }
    }
}

// ---------------- fused Winograd GEMM + inverse transform ----------------
// CTA: 64 oc x 64 tiles, 256 threads = 8 warps (2 M x 4 N), warp tile 32x16.
// Loops j=0..15 serially; per j a K=512 GEMM into macc, then elementwise
// inverse-transform FMA into per-thread fp32 y accumulators. No m intermediate.
#define PAD 40
#define SU_O(buf) ((buf) * 2560)            // 64 * 40 halves per stage
#define SV_O(buf) (7680 + (buf) * 2560)
#define SM_HALVES 15360                     // 30720 bytes

__device__ __forceinline__ void mma_f16(float* c,
                                        const uint32_t* a, uint32_t b0, uint32_t b1) {
    asm volatile(
        "mma.sync.aligned.m16n8k16.row.col.f32.f16.f16.f32 "
        "{%0,%1,%2,%3}, {%4,%5,%6,%7}, {%8,%9}, {%0,%1,%2,%3};"
        : "+f"(c[0]), "+f"(c[1]), "+f"(c[2]), "+f"(c[3])
        : "r"(a[0]), "r"(a[1]), "r"(a[2]), "r"(a[3]), "r"(b0), "r"(b1));
}
__device__ __forceinline__ void ldsm4(uint32_t* r, uint32_t a) {
    asm volatile("ldmatrix.sync.aligned.m8n8.x4.shared.b16 {%0,%1,%2,%3}, [%4];"
                 : "=r"(r[0]), "=r"(r[1]), "=r"(r[2]), "=r"(r[3]) : "r"(a));
}
__device__ __forceinline__ void cp16(uint32_t dst, const void* src) {
    asm volatile("cp.async.ca.shared.global [%0], [%1], 16;"
                 :: "r"(dst), "l"(src) : "memory");
}
#define CP_COMMIT() asm volatile("cp.async.commit_group;" ::: "memory")
#define CP_WAIT0()  asm volatile("cp.async.wait_group 0;" ::: "memory")
#define CP_WAIT1()  asm volatile("cp.async.wait_group 1;" ::: "memory")
__device__ __forceinline__ uint32_t smem_u32(const void* p) {
    uint32_t a;
    asm("{ .reg .u64 t; cvta.to.shared.u64 t, %1; cvt.u32.u64 %0, t; }" : "=r"(a) : "l"(p));
    return a;
}

__global__ __launch_bounds__(256, 2)
void wino_fused_kernel(float* __restrict__ y) {
    extern __shared__ unsigned short sm[];
    const uint32_t smb = smem_u32(sm);
    const int tid = threadIdx.x;
    const int wid = tid >> 5, lane = tid & 31;
    const int gr = lane >> 2, tig = lane & 3;
    const int wM = wid & 1;        // oc half (0/1)
    const int wN = wid >> 1;       // tile quarter (0..3)

    const int nt0 = blockIdx.x * 64;   // tiles
    const int oc0 = blockIdx.y * 64;   // oc

    // ldsm lane address components
    const int r16 = ((lane >> 3) & 1) * 8 + (lane & 7);
    const int kq8 = (lane >> 4) * 8;
    const int aoff = (wM * 32 + r16) * PAD + kq8;
    const int rb = (lane & 7) + ((lane >> 4) & 1) * 8;
    const int kb8 = ((lane >> 3) & 1) * 8;
    const int boff = (wN * 16 + rb) * PAD + kb8;

    // loader: 4 threads per row, 16B each (row = 64B = 32 halves)
    const int rL = tid >> 2, qL = tid & 3;
    const uint32_t udst = (uint32_t)(rL * PAD + qL * 8) * 2;
    const size_t uRow = (size_t)(oc0 + rL) * IC + qL * 8;
    const size_t vRow = (size_t)(nt0 + rL) * IC + qL * 8;

    float macc[2][2][4];
    float yac[2][2][2][8];   // [mt][ntl][rh][t2*4 + r*2 + c]
    #pragma unroll
    for (int a = 0; a < 2; a++)
        #pragma unroll
        for (int bq = 0; bq < 2; bq++) {
            #pragma unroll
            for (int q = 0; q < 4; q++) macc[a][bq][q] = 0.f;
            #pragma unroll
            for (int rh = 0; rh < 2; rh++)
                #pragma unroll
                for (int e = 0; e < 8; e++) yac[a][bq][rh][e] = 0.f;
        }

    // stage s = j*16 + cc  (256 stages), 3-buffer ring, prefetch depth 2
    auto issue = [&](int s, int buf) {
        const int j = s >> 4, cc = s & 15;
        const __half* us = g_U + (size_t)j * OC * IC + uRow + cc * 32;
        const __half* vs = g_V + (size_t)j * NTL * IC + vRow + cc * 32;
        cp16(smb + (uint32_t)SU_O(buf) * 2 + udst, us);
        cp16(smb + (uint32_t)SV_O(buf) * 2 + udst, vs);
    };

    issue(0, 0); CP_COMMIT();
    issue(1, 1); CP_COMMIT();

    for (int s = 0; s < 256; s++) {
        const int j = s >> 4, cc = s & 15;
        if (s < 254) { CP_WAIT1(); } else { CP_WAIT0(); }
        __syncthreads();
        if (s < 254) { issue(s + 2, (s + 2) % 3); CP_COMMIT(); }

        const int buf = s % 3;
        const uint32_t abase = smb + (uint32_t)(SU_O(buf) + aoff) * 2;
        const uint32_t bbase = smb + (uint32_t)(SV_O(buf) + boff) * 2;
        #pragma unroll
        for (int ks = 0; ks < 2; ks++) {
            uint32_t ah[2][4], bh[4];
            ldsm4(ah[0], abase + (uint32_t)(ks * 16) * 2);
            ldsm4(ah[1], abase + (uint32_t)(16 * PAD + ks * 16) * 2);
            ldsm4(bh, bbase + (uint32_t)(ks * 16) * 2);
            mma_f16(macc[0][0], ah[0], bh[0], bh[1]);
            mma_f16(macc[1][0], ah[1], bh[0], bh[1]);
            mma_f16(macc[0][1], ah[0], bh[2], bh[3]);
            mma_f16(macc[1][1], ah[1], bh[2], bh[3]);
        }
        __syncthreads();   // all warps done reading buf before it is refilled

        if (cc == 15) {
            // inverse-transform fold: y[r][c] += ar[r][jr]*ac[c][jc]*m
            const int jr = j >> 2, jc = j & 3;
            const float cr0 = (jr < 3) ? 1.f : 0.f;
            const float cr1 = (jr == 0) ? 0.f : ((jr == 1) ? 1.f : -1.f);
            const float cc0 = (jc < 3) ? 1.f : 0.f;
            const float cc1 = (jc == 0) ? 0.f : ((jc == 1) ? 1.f : -1.f);
            const float p00 = cr0 * cc0, p01 = cr0 * cc1;
            const float p10 = cr1 * cc0, p11 = cr1 * cc1;
            #pragma unroll
            for (int mt = 0; mt < 2; mt++)
                #pragma unroll
                for (int ntl = 0; ntl < 2; ntl++)
                    #pragma unroll
                    for (int rh = 0; rh < 2; rh++)
                        #pragma unroll
                        for (int t2 = 0; t2 < 2; t2++) {
                            float m = macc[mt][ntl][rh * 2 + t2];
                            float* Y = &yac[mt][ntl][rh][t2 * 4];
                            Y[0] = fmaf(p00, m, Y[0]);
                            Y[1] = fmaf(p01, m, Y[1]);
                            Y[2] = fmaf(p10, m, Y[2]);
                            Y[3] = fmaf(p11, m, Y[3]);
                        }
            #pragma unroll
            for (int mt = 0; mt < 2; mt++)
                #pragma unroll
                for (int ntl = 0; ntl < 2; ntl++)
                    #pragma unroll
                    for (int q = 0; q < 4; q++) macc[mt][ntl][q] = 0.f;
        }
    }

    // ---- store: demodulate + write 2x2 output tiles (float2 per row) ----
    #pragma unroll
    for (int mt = 0; mt < 2; mt++)
        #pragma unroll
        for (int rh = 0; rh < 2; rh++) {
            const int oc = oc0 + wM * 32 + mt * 16 + rh * 8 + gr;
            #pragma unroll
            for (int ntl = 0; ntl < 2; ntl++)
                #pragma unroll
                for (int t2 = 0; t2 < 2; t2++) {
                    const int tile = nt0 + wN * 16 + ntl * 8 + tig * 2 + t2;
                    const int b = tile >> 8, ti = (tile >> 4) & 15, tj = tile & 15;
                    const float s = g_scale[b * OC + oc];
                    const float* Y = &yac[mt][ntl][rh][t2 * 4];
                    size_t base = (((size_t)b * OC + oc) * HH + 2 * ti) * WW + 2 * tj;
                    *(float2*)(y + base)      = make_float2(Y[0] * s, Y[1] * s);
                    *(float2*)(y + base + WW) = make_float2(Y[2] * s, Y[3] * s);
                }
        }
}

// ---------------------------------------------------------------------------
extern "C" void kernel_launch(void* const* d_in, const int* in_sizes, int n_in,
                              void* d_out, int out_size) {
    const float* x       = (const float*)d_in[0];
    const float* w       = (const float*)d_in[1];
    const float* conv_w  = (const float*)d_in[2];
    const float* dense_w = (const float*)d_in[3];
    const float* dense_b = (const float*)d_in[4];
    float* y = (float*)d_out;

    style_kernel<<<BN, 256>>>(w, dense_w, dense_b);
    ss_kernel<<<(IC * OC) / 256, 256>>>(conv_w);
    demod_kernel<<<OC / 32, 256>>>();
    uw_kernel<<<dim3(IC / 32, OC / 32), 1024>>>(conv_w);
    vx_kernel<<<BN * 16, 256>>>(x);

    static bool attr_set = false;
    if (!attr_set) {
        cudaFuncSetAttribute(wino_fused_kernel,
                             cudaFuncAttributeMaxDynamicSharedMemorySize, SM_HALVES * 2);
        attr_set = true;
    }
    wino_fused_kernel<<<dim3(NTL / 64, OC / 64), 256, SM_HALVES * 2>>>(y);
}